// round 15
// baseline (speedup 1.0000x reference)
#include <cuda_runtime.h>
#include <cuda_fp16.h>
#include <mma.h>
using namespace nvcuda;

#define NN 100000
#define NNP 100096           // 782*128
#define NE 1600000
#define HID 128
#define OF 64

// ---------------- scratch (device globals; no allocation allowed) ----------
__device__ __half g_x16[NN * HID];    // fp16 copy of x (gather + GEMM source)
__device__ __half g_a16[NNP * HID];   // mean aggregation of x, fp16
__device__ __half g_p16[NNP * OF];    // h @ W2_l.T, fp16 (gather source)
__device__ __half g_q16[NNP * OF];    // h @ W2_r.T, fp16
__device__ __half g_wt1h[256 * HID];  // [W1l;W1r] transposed [k][f], fp16
__device__ __half g_wt2h[HID * HID];  // [W2l|W2r] transposed [k][f], fp16
__device__ int    g_deg[NNP];
__device__ float  g_invdeg[NNP];
__device__ int    g_off[NNP + 1];     // CSR offsets (by dst)
__device__ int    g_cur[NNP];         // counting-sort cursors
__device__ int    g_csrc[NE];         // src sorted by dst
__device__ unsigned long long g_bpack[128];  // lookback: (done<<63)|aggregate

#define CPA16(dst, src) \
    asm volatile("cp.async.cg.shared.global [%0], [%1], 16;" :: "r"(dst), "l"(src))
#define CPA16Z(dst, src, sz) \
    asm volatile("cp.async.cg.shared.global [%0], [%1], 16, %2;" :: "r"(dst), "l"(src), "r"(sz))
#define CPA_COMMIT() asm volatile("cp.async.commit_group;")
#define CPA_WAIT1()  asm volatile("cp.async.wait_group 1;")
#define CPA_WAIT0()  asm volatile("cp.async.wait_group 0;")

// inline dtype detection: int64 edge_index <=> odd int32 words of the first
// 32 entries are all zero (they are hi-words of values < 100000).
__device__ __forceinline__ int detect_is64(const void* ei) {
    unsigned odd = ((const int*)ei)[2 * (threadIdx.x & 31) + 1] != 0;
    unsigned bal = __ballot_sync(0xffffffffu, odd);
    return bal == 0u;
}

__device__ __forceinline__ int ld_edge(const void* ei, long long idx, int is64) {
    return is64 ? (int)((const long long*)ei)[idx] : ((const int*)ei)[idx];
}

// ---------------------------------------------------------------------------
// Fused independent preprocessing (concurrent via block ranges):
//   [0,12500) x->fp16  [12500,18750) degree  [18750,18878) wt1  [...] wt2
// ---------------------------------------------------------------------------
#define PRE_X   12500
#define PRE_DEG 18750
#define PRE_W1  18878
#define PRE_GRID 18942

__global__ void pre_kernel(const float* __restrict__ x, const void* ei,
                           const float* __restrict__ W1l, const float* __restrict__ W1r,
                           const float* __restrict__ W2l, const float* __restrict__ W2r) {
    int b = blockIdx.x;
    int tid = threadIdx.x;
    if (b < PRE_X) {
        int i = b * 256 + tid;
        float4 v = ((const float4*)x)[i];
        __half2 h0 = __floats2half2_rn(v.x, v.y);
        __half2 h1 = __floats2half2_rn(v.z, v.w);
        uint2 u;
        u.x = *(unsigned*)&h0;
        u.y = *(unsigned*)&h1;
        ((uint2*)g_x16)[i] = u;
    } else if (b < PRE_DEG) {
        int is64 = detect_is64(ei);
        int e = (b - PRE_X) * 256 + tid;
        int dst = ld_edge(ei, (long long)NE + e, is64);
        atomicAdd(&g_deg[dst], 1);
    } else if (b < PRE_W1) {
        int i = (b - PRE_DEG) * 256 + tid;
        int k = i >> 7, f = i & 127;
        float v = (k < 128) ? W1l[f * 128 + k] : W1r[f * 128 + (k - 128)];
        g_wt1h[k * 128 + f] = __float2half_rn(v);
    } else {
        int i = (b - PRE_W1) * 256 + tid;
        int k = i >> 7, f = i & 127;
        float v = (f < 64) ? W2l[f * 128 + k] : W2r[(f - 64) * 128 + k];
        g_wt2h[k * 128 + f] = __float2half_rn(v);
    }
}

// ---------------------------------------------------------------------------
// Single-pass decoupled-lookback scan of degrees -> g_off, g_cur, g_invdeg.
// ---------------------------------------------------------------------------
__global__ void scan_kernel() {
    __shared__ int wsum[32];
    __shared__ int spfx;
    int b = blockIdx.x, t = threadIdx.x;
    int i = b * 1024 + t;
    int lane = t & 31, warp = t >> 5;
    int d = (i < NNP) ? g_deg[i] : 0;
    int v = d;
#pragma unroll
    for (int o = 1; o < 32; o <<= 1) {
        int n = __shfl_up_sync(0xffffffffu, v, o);
        if (lane >= o) v += n;
    }
    if (lane == 31) wsum[warp] = v;
    __syncthreads();
    if (warp == 0) {
        int wv = wsum[lane];
#pragma unroll
        for (int o = 1; o < 32; o <<= 1) {
            int n = __shfl_up_sync(0xffffffffu, wv, o);
            if (lane >= o) wv += n;
        }
        wsum[lane] = wv;
    }
    __syncthreads();
    int incl = v + (warp ? wsum[warp - 1] : 0);

    if (t == 1023)
        atomicExch(&g_bpack[b], (1ULL << 63) | (unsigned long long)(unsigned)incl);

    if (warp == 0) {
        int s = 0;
        for (int j = lane; j < b; j += 32) {
            unsigned long long pv;
            do { pv = atomicAdd(&g_bpack[j], 0ULL); } while (!(pv >> 63));
            s += (int)(unsigned)pv;
        }
#pragma unroll
        for (int o = 16; o > 0; o >>= 1) s += __shfl_down_sync(0xffffffffu, s, o);
        if (lane == 0) spfx = s;
    }
    __syncthreads();
    int pfx = spfx;
    if (i < NNP) {
        int inclg = incl + pfx;
        g_off[i + 1] = inclg;
        g_cur[i] = inclg - d;
        g_invdeg[i] = 1.0f / fmaxf((float)d, 1.0f);
        if (i == 0) g_off[0] = 0;
    }
}

// ---------------------------------------------------------------------------
// counting sort: csrc sorted by dst
// ---------------------------------------------------------------------------
__global__ void sort_kernel(const void* ei) {
    int is64 = detect_is64(ei);
    int e = blockIdx.x * blockDim.x + threadIdx.x;
    if (e < NE) {
        int src = ld_edge(ei, e, is64);
        int dst = ld_edge(ei, (long long)NE + e, is64);
        int pos = atomicAdd(&g_cur[dst], 1);
        g_csrc[pos] = src;
    }
}

// ---------------------------------------------------------------------------
// CSR mean-aggregate x16 -> g_a16. Half-warp processes 8 CONSECUTIVE nodes
// (Poisson pooling smooths load imbalance; block = 128 nodes).
// Inner loop is the measured-best R10 body.
// ---------------------------------------------------------------------------
__global__ void agg1_kernel() {
    int hw = (blockIdx.x * blockDim.x + threadIdx.x) >> 4;   // half-warp id
    int sub = threadIdx.x & 15;
    int n0 = hw * 8;
    if (n0 >= NNP) return;
    const uint4* X = (const uint4*)g_x16;    // row = 16 uint4
    for (int nv = 0; nv < 8; nv++) {
        int gw = n0 + nv;
        int beg = g_off[gw], end = g_off[gw + 1];
        float a[8] = {0.f, 0.f, 0.f, 0.f, 0.f, 0.f, 0.f, 0.f};
        float c[8] = {0.f, 0.f, 0.f, 0.f, 0.f, 0.f, 0.f, 0.f};
        int e = beg;
        for (; e + 7 < end; e += 8) {
            uint4 u[8];
#pragma unroll
            for (int j = 0; j < 8; j++)
                u[j] = __ldg(&X[(size_t)g_csrc[e + j] * 16 + sub]);
#pragma unroll
            for (int j = 0; j < 8; j += 2) {
                float2 f;
                f = __half22float2(*(__half2*)&u[j].x);     a[0] += f.x; a[1] += f.y;
                f = __half22float2(*(__half2*)&u[j].y);     a[2] += f.x; a[3] += f.y;
                f = __half22float2(*(__half2*)&u[j].z);     a[4] += f.x; a[5] += f.y;
                f = __half22float2(*(__half2*)&u[j].w);     a[6] += f.x; a[7] += f.y;
                f = __half22float2(*(__half2*)&u[j + 1].x); c[0] += f.x; c[1] += f.y;
                f = __half22float2(*(__half2*)&u[j + 1].y); c[2] += f.x; c[3] += f.y;
                f = __half22float2(*(__half2*)&u[j + 1].z); c[4] += f.x; c[5] += f.y;
                f = __half22float2(*(__half2*)&u[j + 1].w); c[6] += f.x; c[7] += f.y;
            }
        }
        for (; e + 3 < end; e += 4) {
            uint4 u[4];
#pragma unroll
            for (int j = 0; j < 4; j++)
                u[j] = __ldg(&X[(size_t)g_csrc[e + j] * 16 + sub]);
#pragma unroll
            for (int j = 0; j < 4; j += 2) {
                float2 f;
                f = __half22float2(*(__half2*)&u[j].x);     a[0] += f.x; a[1] += f.y;
                f = __half22float2(*(__half2*)&u[j].y);     a[2] += f.x; a[3] += f.y;
                f = __half22float2(*(__half2*)&u[j].z);     a[4] += f.x; a[5] += f.y;
                f = __half22float2(*(__half2*)&u[j].w);     a[6] += f.x; a[7] += f.y;
                f = __half22float2(*(__half2*)&u[j + 1].x); c[0] += f.x; c[1] += f.y;
                f = __half22float2(*(__half2*)&u[j + 1].y); c[2] += f.x; c[3] += f.y;
                f = __half22float2(*(__half2*)&u[j + 1].z); c[4] += f.x; c[5] += f.y;
                f = __half22float2(*(__half2*)&u[j + 1].w); c[6] += f.x; c[7] += f.y;
            }
        }
        for (; e < end; e++) {
            uint4 u = __ldg(&X[(size_t)g_csrc[e] * 16 + sub]);
            float2 f;
            f = __half22float2(*(__half2*)&u.x); a[0] += f.x; a[1] += f.y;
            f = __half22float2(*(__half2*)&u.y); a[2] += f.x; a[3] += f.y;
            f = __half22float2(*(__half2*)&u.z); a[4] += f.x; a[5] += f.y;
            f = __half22float2(*(__half2*)&u.w); a[6] += f.x; a[7] += f.y;
        }
        float inv = g_invdeg[gw];
        __half2 h0 = __floats2half2_rn((a[0] + c[0]) * inv, (a[1] + c[1]) * inv);
        __half2 h1 = __floats2half2_rn((a[2] + c[2]) * inv, (a[3] + c[3]) * inv);
        __half2 h2 = __floats2half2_rn((a[4] + c[4]) * inv, (a[5] + c[5]) * inv);
        __half2 h3 = __floats2half2_rn((a[6] + c[6]) * inv, (a[7] + c[7]) * inv);
        uint4 o;
        o.x = *(unsigned*)&h0;
        o.y = *(unsigned*)&h1;
        o.z = *(unsigned*)&h2;
        o.w = *(unsigned*)&h3;
        ((uint4*)g_a16)[(size_t)gw * 16 + sub] = o;
    }
}

// ---------------------------------------------------------------------------
// CSR mean-aggregate p16 + q16 + b2 -> out. Half-warp x 8 nodes (pooled).
// ---------------------------------------------------------------------------
__global__ void agg2_final_kernel(const float* __restrict__ b2,
                                  float* __restrict__ out) {
    int hw = (blockIdx.x * blockDim.x + threadIdx.x) >> 4;
    int sub = threadIdx.x & 15;
    int n0 = hw * 8;
    if (n0 >= NN) return;
    const uint2* P = (const uint2*)g_p16;    // row = 16 uint2
    float4 bb = ((const float4*)b2)[sub];
    int nmax = (NN - n0 < 8) ? (NN - n0) : 8;
    for (int nv = 0; nv < nmax; nv++) {
        int gw = n0 + nv;
        int beg = g_off[gw], end = g_off[gw + 1];
        float a[4] = {0.f, 0.f, 0.f, 0.f};
        float c[4] = {0.f, 0.f, 0.f, 0.f};
        int e = beg;
        for (; e + 7 < end; e += 8) {
            uint2 u[8];
#pragma unroll
            for (int j = 0; j < 8; j++)
                u[j] = __ldg(&P[(size_t)g_csrc[e + j] * 16 + sub]);
#pragma unroll
            for (int j = 0; j < 8; j += 2) {
                float2 f;
                f = __half22float2(*(__half2*)&u[j].x);     a[0] += f.x; a[1] += f.y;
                f = __half22float2(*(__half2*)&u[j].y);     a[2] += f.x; a[3] += f.y;
                f = __half22float2(*(__half2*)&u[j + 1].x); c[0] += f.x; c[1] += f.y;
                f = __half22float2(*(__half2*)&u[j + 1].y); c[2] += f.x; c[3] += f.y;
            }
        }
        for (; e + 3 < end; e += 4) {
            uint2 u[4];
#pragma unroll
            for (int j = 0; j < 4; j++)
                u[j] = __ldg(&P[(size_t)g_csrc[e + j] * 16 + sub]);
#pragma unroll
            for (int j = 0; j < 4; j += 2) {
                float2 f;
                f = __half22float2(*(__half2*)&u[j].x);     a[0] += f.x; a[1] += f.y;
                f = __half22float2(*(__half2*)&u[j].y);     a[2] += f.x; a[3] += f.y;
                f = __half22float2(*(__half2*)&u[j + 1].x); c[0] += f.x; c[1] += f.y;
                f = __half22float2(*(__half2*)&u[j + 1].y); c[2] += f.x; c[3] += f.y;
            }
        }
        for (; e < end; e++) {
            uint2 u = __ldg(&P[(size_t)g_csrc[e] * 16 + sub]);
            float2 f;
            f = __half22float2(*(__half2*)&u.x); a[0] += f.x; a[1] += f.y;
            f = __half22float2(*(__half2*)&u.y); a[2] += f.x; a[3] += f.y;
        }
        float inv = g_invdeg[gw];
        uint2 qu = ((const uint2*)g_q16)[(size_t)gw * 16 + sub];
        float2 q0 = __half22float2(*(__half2*)&qu.x);
        float2 q1 = __half22float2(*(__half2*)&qu.y);
        float4 o;
        o.x = (a[0] + c[0]) * inv + q0.x + bb.x;
        o.y = (a[1] + c[1]) * inv + q0.y + bb.y;
        o.z = (a[2] + c[2]) * inv + q1.x + bb.z;
        o.w = (a[3] + c[3]) * inv + q1.y + bb.w;
        ((float4*)out)[(size_t)gw * 16 + sub] = o;
    }
}

// ---------------------------------------------------------------------------
// Fused layer-1 + layer-2 GEMM (R10 version, measured best):
//   h = relu(BN([a16|x16] @ Wt1 + b1)) (smem only); [p16|q16] = h @ Wt2
// ---------------------------------------------------------------------------
#define ALDH 72
#define WLDH 136
#define CLD  136
#define BUFH (128 * ALDH + 64 * WLDH)        // 17920 halfs per buffer
#define HS_OFF   (2 * BUFH)
#define WT2_OFF  (HS_OFF + 128 * WLDH)
#define BN_BYTE  ((WT2_OFF + 128 * WLDH) * 2)
#define SM_BYTES (BN_BYTE + 1024)

__global__ void __launch_bounds__(256, 1) gemm12_kernel(
    const float* __restrict__ b1, const float* __restrict__ gmm,
    const float* __restrict__ bet, const float* __restrict__ mean,
    const float* __restrict__ var)
{
    extern __shared__ __align__(16) char smraw[];
    __half* smh = (__half*)smraw;
    float* Cs = (float*)smraw;                 // union with ping-pong buffers
    __half* Hs = smh + HS_OFF;
    __half* W2s = smh + WT2_OFF;
    float* Ssc = (float*)(smraw + BN_BYTE);
    float* Ssh = Ssc + 128;

    const int tid = threadIdx.x;
    const int wid = tid >> 5;
    const int wm = wid >> 1;
    const int wn = wid & 1;
    const int n0 = blockIdx.x * 128;
    const unsigned smu = (unsigned)__cvta_generic_to_shared(smraw);

    if (tid < 128) {
        float s = rsqrtf(var[tid] + 1e-5f) * gmm[tid];
        Ssc[tid] = s;
        Ssh[tid] = (b1[tid] - mean[tid]) * s + bet[tid];
    }

    wmma::fragment<wmma::accumulator, 16, 16, 16, float> acc[2][4];
#pragma unroll
    for (int i = 0; i < 2; i++)
#pragma unroll
        for (int j = 0; j < 4; j++) wmma::fill_fragment(acc[i][j], 0.f);

    const __half* A16 = g_a16;
    const __half* X16 = g_x16;
    const __half* WT = g_wt1h;

    auto stage = [&](int kc, int bufi) {
        unsigned base = smu + (unsigned)(bufi * BUFH * 2);
#pragma unroll
        for (int it = 0; it < 4; it++) {
            int t = tid + it * 256;          // 1024 chunks of 8 halfs
            int row = t >> 3, q = t & 7;
            int gn = n0 + row;
            unsigned dst = base + (unsigned)((row * ALDH + q * 8) * 2);
            if (kc < 2) {
                CPA16(dst, A16 + (size_t)gn * HID + kc * 64 + q * 8);
            } else {
                int sz = (gn < NN) ? 16 : 0;
                CPA16Z(dst, X16 + (size_t)gn * HID + (kc - 2) * 64 + q * 8, sz);
            }
        }
#pragma unroll
        for (int it = 0; it < 4; it++) {
            int t = tid + it * 256;          // 1024 chunks: 64 k-rows x 16
            int kr = t >> 4, fq = t & 15;
            unsigned dst = base + (unsigned)((128 * ALDH + kr * WLDH + fq * 8) * 2);
            CPA16(dst, WT + (size_t)(kc * 64 + kr) * HID + fq * 8);
        }
    };

    // prefetch Wt2 (128x128) into W2s as part of the first commit group
#pragma unroll
    for (int it = 0; it < 8; it++) {
        int t = tid + it * 256;              // 2048 chunks
        int kr = t >> 4, fq = t & 15;
        unsigned dst = smu + (unsigned)((WT2_OFF + kr * WLDH + fq * 8) * 2);
        CPA16(dst, g_wt2h + (size_t)kr * HID + fq * 8);
    }
    stage(0, 0);
    CPA_COMMIT();

    // ---- layer 1: K = 256 in 4 chunks of 64 ----
    for (int kc = 0; kc < 4; kc++) {
        int cur = kc & 1;
        if (kc < 3) stage(kc + 1, cur ^ 1);
        CPA_COMMIT();
        if (kc < 3) CPA_WAIT1(); else CPA_WAIT0();
        __syncthreads();

        __half* As = smh + cur * BUFH;
        __half* Ws = As + 128 * ALDH;
#pragma unroll
        for (int k16 = 0; k16 < 4; k16++) {
            wmma::fragment<wmma::matrix_a, 16, 16, 16, __half, wmma::row_major> a[2];
#pragma unroll
            for (int i = 0; i < 2; i++)
                wmma::load_matrix_sync(a[i], As + (wm * 32 + i * 16) * ALDH + k16 * 16, ALDH);
#pragma unroll
            for (int nf = 0; nf < 4; nf++) {
                wmma::fragment<wmma::matrix_b, 16, 16, 16, __half, wmma::row_major> b;
                wmma::load_matrix_sync(b, Ws + (k16 * 16) * WLDH + wn * 64 + nf * 16, WLDH);
#pragma unroll
                for (int i = 0; i < 2; i++)
                    wmma::mma_sync(acc[i][nf], a[i], b, acc[i][nf]);
            }
        }
        __syncthreads();
    }

    // ---- layer-1 epilogue: acc -> Cs -> BN+ReLU -> Hs (fp16, smem only) ----
#pragma unroll
    for (int i = 0; i < 2; i++)
#pragma unroll
        for (int nf = 0; nf < 4; nf++)
            wmma::store_matrix_sync(Cs + (wm * 32 + i * 16) * CLD + wn * 64 + nf * 16,
                                    acc[i][nf], CLD, wmma::mem_row_major);
    __syncthreads();
    {
        int row = tid >> 1, half = tid & 1;
        const float* src = Cs + row * CLD + half * 64;
        __half2* dst = (__half2*)(Hs + row * WLDH + half * 64);
#pragma unroll
        for (int j = 0; j < 16; j++) {
            float4 v = *(const float4*)(src + j * 4);
            int f = half * 64 + j * 4;
            float o0 = fmaxf(v.x * Ssc[f + 0] + Ssh[f + 0], 0.f);
            float o1 = fmaxf(v.y * Ssc[f + 1] + Ssh[f + 1], 0.f);
            float o2 = fmaxf(v.z * Ssc[f + 2] + Ssh[f + 2], 0.f);
            float o3 = fmaxf(v.w * Ssc[f + 3] + Ssh[f + 3], 0.f);
            dst[j * 2 + 0] = __floats2half2_rn(o0, o1);
            dst[j * 2 + 1] = __floats2half2_rn(o2, o3);
        }
    }
    __syncthreads();

    // ---- layer 2: [p|q] = Hs @ W2s (all operands in smem) ----
#pragma unroll
    for (int i = 0; i < 2; i++)
#pragma unroll
        for (int j = 0; j < 4; j++) wmma::fill_fragment(acc[i][j], 0.f);
#pragma unroll
    for (int k16 = 0; k16 < 8; k16++) {
        wmma::fragment<wmma::matrix_a, 16, 16, 16, __half, wmma::row_major> a[2];
#pragma unroll
        for (int i = 0; i < 2; i++)
            wmma::load_matrix_sync(a[i], Hs + (wm * 32 + i * 16) * WLDH + k16 * 16, WLDH);
#pragma unroll
        for (int nf = 0; nf < 4; nf++) {
            wmma::fragment<wmma::matrix_b, 16, 16, 16, __half, wmma::row_major> b;
            wmma::load_matrix_sync(b, W2s + (k16 * 16) * WLDH + wn * 64 + nf * 16, WLDH);
#pragma unroll
            for (int i = 0; i < 2; i++)
                wmma::mma_sync(acc[i][nf], a[i], b, acc[i][nf]);
        }
    }

    // ---- layer-2 epilogue: p cols [0,64) and q cols [64,128), both fp16 ----
#pragma unroll
    for (int i = 0; i < 2; i++)
#pragma unroll
        for (int nf = 0; nf < 4; nf++)
            wmma::store_matrix_sync(Cs + (wm * 32 + i * 16) * CLD + wn * 64 + nf * 16,
                                    acc[i][nf], CLD, wmma::mem_row_major);
    __syncthreads();
    {
        int row = tid >> 1, half = tid & 1;
        int gn = n0 + row;
        const float* src = Cs + row * CLD + half * 64;
        uint2* dst = half ? (uint2*)(g_q16 + (size_t)gn * OF)
                          : (uint2*)(g_p16 + (size_t)gn * OF);
#pragma unroll
        for (int j = 0; j < 16; j++) {
            float4 v = *(const float4*)(src + j * 4);
            __half2 h0 = __floats2half2_rn(v.x, v.y);
            __half2 h1 = __floats2half2_rn(v.z, v.w);
            uint2 u;
            u.x = *(unsigned*)&h0;
            u.y = *(unsigned*)&h1;
            dst[j] = u;
        }
    }
}

// ---------------------------------------------------------------------------
// Launch
// ---------------------------------------------------------------------------
extern "C" void kernel_launch(void* const* d_in, const int* in_sizes, int n_in,
                              void* d_out, int out_size) {
    const float* x    = (const float*)d_in[0];
    const void*  ei   = d_in[1];
    const float* W1l  = (const float*)d_in[2];
    const float* b1   = (const float*)d_in[3];
    const float* W1r  = (const float*)d_in[4];
    const float* gmm  = (const float*)d_in[5];
    const float* bet  = (const float*)d_in[6];
    const float* mean = (const float*)d_in[7];
    const float* var  = (const float*)d_in[8];
    const float* W2l  = (const float*)d_in[9];
    const float* b2   = (const float*)d_in[10];
    const float* W2r  = (const float*)d_in[11];
    float* out = (float*)d_out;

    cudaFuncSetAttribute(gemm12_kernel, cudaFuncAttributeMaxDynamicSharedMemorySize, SM_BYTES);

    void* degp = 0;
    void* bpackp = 0;
    cudaGetSymbolAddress(&degp, g_deg);
    cudaGetSymbolAddress(&bpackp, g_bpack);

    cudaMemsetAsync(degp, 0, sizeof(int) * NNP, 0);
    cudaMemsetAsync(bpackp, 0, sizeof(unsigned long long) * 128, 0);
    pre_kernel<<<PRE_GRID, 256>>>(x, ei, W1l, W1r, W2l, W2r);

    scan_kernel<<<98, 1024>>>();
    sort_kernel<<<(NE + 255) / 256, 256>>>(ei);
    agg1_kernel<<<NNP / 128, 256>>>();          // 782 blocks, 8 nodes/half-warp

    gemm12_kernel<<<NNP / 128, 256, SM_BYTES>>>(b1, gmm, bet, mean, var);
    agg2_final_kernel<<<(NN + 127) / 128, 256>>>(b2, out);
}

// round 16
// speedup vs baseline: 1.1143x; 1.1143x over previous
#include <cuda_runtime.h>
#include <cuda_fp16.h>
#include <mma.h>
using namespace nvcuda;

#define NN 100000
#define NNP 100096           // 782*128
#define NE 1600000
#define HID 128
#define OF 64

// ---------------- scratch (device globals; no allocation allowed) ----------
__device__ __half g_x16[NN * HID];    // fp16 copy of x (gather + GEMM source)
__device__ __half g_a16[NNP * HID];   // mean aggregation of x, fp16
__device__ __half g_p16[NNP * OF];    // h @ W2_l.T, fp16 (gather source)
__device__ __half g_q16[NNP * OF];    // h @ W2_r.T, fp16
__device__ __half g_wt1h[256 * HID];  // [W1l;W1r] transposed [k][f], fp16
__device__ __half g_wt2h[HID * HID];  // [W2l|W2r] transposed [k][f], fp16
__device__ int    g_deg[NNP];
__device__ float  g_invdeg[NNP];
__device__ int    g_off[NNP + 1];     // CSR offsets (by dst)
__device__ int    g_cur[NNP];         // counting-sort cursors
__device__ int    g_csrc[NE];         // src sorted by dst
__device__ unsigned long long g_bpack[128];  // lookback: (done<<63)|aggregate

#define CPA16(dst, src) \
    asm volatile("cp.async.cg.shared.global [%0], [%1], 16;" :: "r"(dst), "l"(src))
#define CPA16Z(dst, src, sz) \
    asm volatile("cp.async.cg.shared.global [%0], [%1], 16, %2;" :: "r"(dst), "l"(src), "r"(sz))
#define CPA_COMMIT() asm volatile("cp.async.commit_group;")
#define CPA_WAIT1()  asm volatile("cp.async.wait_group 1;")
#define CPA_WAIT0()  asm volatile("cp.async.wait_group 0;")

// inline dtype detection: int64 edge_index <=> odd int32 words of the first
// 32 entries are all zero (they are hi-words of values < 100000).
__device__ __forceinline__ int detect_is64(const void* ei) {
    unsigned odd = ((const int*)ei)[2 * (threadIdx.x & 31) + 1] != 0;
    unsigned bal = __ballot_sync(0xffffffffu, odd);
    return bal == 0u;
}

// ---------------------------------------------------------------------------
// Fused independent preprocessing (concurrent via block ranges):
//   [0,12500) x->fp16  [12500,15625) degree(2 edges/thr)  [..] wt1  [..] wt2
// ---------------------------------------------------------------------------
#define PRE_X   12500
#define PRE_DEG 15625
#define PRE_W1  15753
#define PRE_GRID 15817

__global__ void pre_kernel(const float* __restrict__ x, const void* ei,
                           const float* __restrict__ W1l, const float* __restrict__ W1r,
                           const float* __restrict__ W2l, const float* __restrict__ W2r) {
    int b = blockIdx.x;
    int tid = threadIdx.x;
    if (b < PRE_X) {
        int i = b * 256 + tid;
        float4 v = ((const float4*)x)[i];
        __half2 h0 = __floats2half2_rn(v.x, v.y);
        __half2 h1 = __floats2half2_rn(v.z, v.w);
        uint2 u;
        u.x = *(unsigned*)&h0;
        u.y = *(unsigned*)&h1;
        ((uint2*)g_x16)[i] = u;
    } else if (b < PRE_DEG) {
        int is64 = detect_is64(ei);
        int e2 = ((b - PRE_X) * 256 + tid) * 2;   // two edges
        int d0, d1;
        if (is64) {
            longlong2 p = __ldg((const longlong2*)((const long long*)ei + NE) + (e2 >> 1));
            d0 = (int)p.x; d1 = (int)p.y;
        } else {
            int2 p = __ldg((const int2*)((const int*)ei + NE) + (e2 >> 1));
            d0 = p.x; d1 = p.y;
        }
        atomicAdd(&g_deg[d0], 1);
        atomicAdd(&g_deg[d1], 1);
    } else if (b < PRE_W1) {
        int i = (b - PRE_DEG) * 256 + tid;
        int k = i >> 7, f = i & 127;
        float v = (k < 128) ? W1l[f * 128 + k] : W1r[f * 128 + (k - 128)];
        g_wt1h[k * 128 + f] = __float2half_rn(v);
    } else {
        int i = (b - PRE_W1) * 256 + tid;
        int k = i >> 7, f = i & 127;
        float v = (f < 64) ? W2l[f * 128 + k] : W2r[(f - 64) * 128 + k];
        g_wt2h[k * 128 + f] = __float2half_rn(v);
    }
}

// ---------------------------------------------------------------------------
// Single-pass decoupled-lookback scan of degrees -> g_off, g_cur, g_invdeg.
// ---------------------------------------------------------------------------
__global__ void scan_kernel() {
    __shared__ int wsum[32];
    __shared__ int spfx;
    int b = blockIdx.x, t = threadIdx.x;
    int i = b * 1024 + t;
    int lane = t & 31, warp = t >> 5;
    int d = (i < NNP) ? g_deg[i] : 0;
    int v = d;
#pragma unroll
    for (int o = 1; o < 32; o <<= 1) {
        int n = __shfl_up_sync(0xffffffffu, v, o);
        if (lane >= o) v += n;
    }
    if (lane == 31) wsum[warp] = v;
    __syncthreads();
    if (warp == 0) {
        int wv = wsum[lane];
#pragma unroll
        for (int o = 1; o < 32; o <<= 1) {
            int n = __shfl_up_sync(0xffffffffu, wv, o);
            if (lane >= o) wv += n;
        }
        wsum[lane] = wv;
    }
    __syncthreads();
    int incl = v + (warp ? wsum[warp - 1] : 0);

    if (t == 1023)
        atomicExch(&g_bpack[b], (1ULL << 63) | (unsigned long long)(unsigned)incl);

    if (warp == 0) {
        int s = 0;
        for (int j = lane; j < b; j += 32) {
            unsigned long long pv;
            do { pv = atomicAdd(&g_bpack[j], 0ULL); } while (!(pv >> 63));
            s += (int)(unsigned)pv;
        }
#pragma unroll
        for (int o = 16; o > 0; o >>= 1) s += __shfl_down_sync(0xffffffffu, s, o);
        if (lane == 0) spfx = s;
    }
    __syncthreads();
    int pfx = spfx;
    if (i < NNP) {
        int inclg = incl + pfx;
        g_off[i + 1] = inclg;
        g_cur[i] = inclg - d;
        g_invdeg[i] = 1.0f / fmaxf((float)d, 1.0f);
        if (i == 0) g_off[0] = 0;
    }
}

// ---------------------------------------------------------------------------
// counting sort: csrc sorted by dst. 2 edges per thread, vector loads.
// ---------------------------------------------------------------------------
__global__ void sort_kernel(const void* ei) {
    int is64 = detect_is64(ei);
    int e2 = (blockIdx.x * blockDim.x + threadIdx.x) * 2;
    if (e2 >= NE) return;
    int s0, s1, d0, d1;
    if (is64) {
        longlong2 ps = __ldg((const longlong2*)ei + (e2 >> 1));
        longlong2 pd = __ldg((const longlong2*)((const long long*)ei + NE) + (e2 >> 1));
        s0 = (int)ps.x; s1 = (int)ps.y;
        d0 = (int)pd.x; d1 = (int)pd.y;
    } else {
        int2 ps = __ldg((const int2*)ei + (e2 >> 1));
        int2 pd = __ldg((const int2*)((const int*)ei + NE) + (e2 >> 1));
        s0 = ps.x; s1 = ps.y;
        d0 = pd.x; d1 = pd.y;
    }
    int p0 = atomicAdd(&g_cur[d0], 1);
    g_csrc[p0] = s0;
    int p1 = atomicAdd(&g_cur[d1], 1);
    g_csrc[p1] = s1;
}

// ---------------------------------------------------------------------------
// CSR mean-aggregate x16 -> g_a16. HALF-WARP per node: 16 lanes x uint4.
// (R10 version — measured best)
// ---------------------------------------------------------------------------
__global__ void agg1_kernel() {
    int gw = (blockIdx.x * blockDim.x + threadIdx.x) >> 4;   // node
    int sub = threadIdx.x & 15;
    if (gw >= NNP) return;
    int beg = g_off[gw], end = g_off[gw + 1];
    const uint4* X = (const uint4*)g_x16;    // row = 16 uint4
    float a[8] = {0.f, 0.f, 0.f, 0.f, 0.f, 0.f, 0.f, 0.f};
    float c[8] = {0.f, 0.f, 0.f, 0.f, 0.f, 0.f, 0.f, 0.f};
    int e = beg;
    for (; e + 7 < end; e += 8) {
        uint4 u[8];
#pragma unroll
        for (int j = 0; j < 8; j++)
            u[j] = __ldg(&X[(size_t)g_csrc[e + j] * 16 + sub]);
#pragma unroll
        for (int j = 0; j < 8; j += 2) {
            float2 f;
            f = __half22float2(*(__half2*)&u[j].x);     a[0] += f.x; a[1] += f.y;
            f = __half22float2(*(__half2*)&u[j].y);     a[2] += f.x; a[3] += f.y;
            f = __half22float2(*(__half2*)&u[j].z);     a[4] += f.x; a[5] += f.y;
            f = __half22float2(*(__half2*)&u[j].w);     a[6] += f.x; a[7] += f.y;
            f = __half22float2(*(__half2*)&u[j + 1].x); c[0] += f.x; c[1] += f.y;
            f = __half22float2(*(__half2*)&u[j + 1].y); c[2] += f.x; c[3] += f.y;
            f = __half22float2(*(__half2*)&u[j + 1].z); c[4] += f.x; c[5] += f.y;
            f = __half22float2(*(__half2*)&u[j + 1].w); c[6] += f.x; c[7] += f.y;
        }
    }
    for (; e + 3 < end; e += 4) {
        uint4 u[4];
#pragma unroll
        for (int j = 0; j < 4; j++)
            u[j] = __ldg(&X[(size_t)g_csrc[e + j] * 16 + sub]);
#pragma unroll
        for (int j = 0; j < 4; j += 2) {
            float2 f;
            f = __half22float2(*(__half2*)&u[j].x);     a[0] += f.x; a[1] += f.y;
            f = __half22float2(*(__half2*)&u[j].y);     a[2] += f.x; a[3] += f.y;
            f = __half22float2(*(__half2*)&u[j].z);     a[4] += f.x; a[5] += f.y;
            f = __half22float2(*(__half2*)&u[j].w);     a[6] += f.x; a[7] += f.y;
            f = __half22float2(*(__half2*)&u[j + 1].x); c[0] += f.x; c[1] += f.y;
            f = __half22float2(*(__half2*)&u[j + 1].y); c[2] += f.x; c[3] += f.y;
            f = __half22float2(*(__half2*)&u[j + 1].z); c[4] += f.x; c[5] += f.y;
            f = __half22float2(*(__half2*)&u[j + 1].w); c[6] += f.x; c[7] += f.y;
        }
    }
    for (; e < end; e++) {
        uint4 u = __ldg(&X[(size_t)g_csrc[e] * 16 + sub]);
        float2 f;
        f = __half22float2(*(__half2*)&u.x); a[0] += f.x; a[1] += f.y;
        f = __half22float2(*(__half2*)&u.y); a[2] += f.x; a[3] += f.y;
        f = __half22float2(*(__half2*)&u.z); a[4] += f.x; a[5] += f.y;
        f = __half22float2(*(__half2*)&u.w); a[6] += f.x; a[7] += f.y;
    }
    float inv = g_invdeg[gw];
    __half2 h0 = __floats2half2_rn((a[0] + c[0]) * inv, (a[1] + c[1]) * inv);
    __half2 h1 = __floats2half2_rn((a[2] + c[2]) * inv, (a[3] + c[3]) * inv);
    __half2 h2 = __floats2half2_rn((a[4] + c[4]) * inv, (a[5] + c[5]) * inv);
    __half2 h3 = __floats2half2_rn((a[6] + c[6]) * inv, (a[7] + c[7]) * inv);
    uint4 o;
    o.x = *(unsigned*)&h0;
    o.y = *(unsigned*)&h1;
    o.z = *(unsigned*)&h2;
    o.w = *(unsigned*)&h3;
    ((uint4*)g_a16)[(size_t)gw * 16 + sub] = o;
}

// ---------------------------------------------------------------------------
// CSR mean-aggregate p16 + q16 + b2 -> out. HALF-WARP per node (R10 version).
// ---------------------------------------------------------------------------
__global__ void agg2_final_kernel(const float* __restrict__ b2,
                                  float* __restrict__ out) {
    int gw = (blockIdx.x * blockDim.x + threadIdx.x) >> 4;   // node
    int sub = threadIdx.x & 15;
    if (gw >= NN) return;
    int beg = g_off[gw], end = g_off[gw + 1];
    const uint2* P = (const uint2*)g_p16;    // row = 16 uint2
    float a[4] = {0.f, 0.f, 0.f, 0.f};
    float c[4] = {0.f, 0.f, 0.f, 0.f};
    int e = beg;
    for (; e + 7 < end; e += 8) {
        uint2 u[8];
#pragma unroll
        for (int j = 0; j < 8; j++)
            u[j] = __ldg(&P[(size_t)g_csrc[e + j] * 16 + sub]);
#pragma unroll
        for (int j = 0; j < 8; j += 2) {
            float2 f;
            f = __half22float2(*(__half2*)&u[j].x);     a[0] += f.x; a[1] += f.y;
            f = __half22float2(*(__half2*)&u[j].y);     a[2] += f.x; a[3] += f.y;
            f = __half22float2(*(__half2*)&u[j + 1].x); c[0] += f.x; c[1] += f.y;
            f = __half22float2(*(__half2*)&u[j + 1].y); c[2] += f.x; c[3] += f.y;
        }
    }
    for (; e + 3 < end; e += 4) {
        uint2 u[4];
#pragma unroll
        for (int j = 0; j < 4; j++)
            u[j] = __ldg(&P[(size_t)g_csrc[e + j] * 16 + sub]);
#pragma unroll
        for (int j = 0; j < 4; j += 2) {
            float2 f;
            f = __half22float2(*(__half2*)&u[j].x);     a[0] += f.x; a[1] += f.y;
            f = __half22float2(*(__half2*)&u[j].y);     a[2] += f.x; a[3] += f.y;
            f = __half22float2(*(__half2*)&u[j + 1].x); c[0] += f.x; c[1] += f.y;
            f = __half22float2(*(__half2*)&u[j + 1].y); c[2] += f.x; c[3] += f.y;
        }
    }
    for (; e < end; e++) {
        uint2 u = __ldg(&P[(size_t)g_csrc[e] * 16 + sub]);
        float2 f;
        f = __half22float2(*(__half2*)&u.x); a[0] += f.x; a[1] += f.y;
        f = __half22float2(*(__half2*)&u.y); a[2] += f.x; a[3] += f.y;
    }
    float inv = g_invdeg[gw];
    uint2 qu = ((const uint2*)g_q16)[(size_t)gw * 16 + sub];
    float2 q0 = __half22float2(*(__half2*)&qu.x);
    float2 q1 = __half22float2(*(__half2*)&qu.y);
    float4 bb = ((const float4*)b2)[sub];
    float4 o;
    o.x = (a[0] + c[0]) * inv + q0.x + bb.x;
    o.y = (a[1] + c[1]) * inv + q0.y + bb.y;
    o.z = (a[2] + c[2]) * inv + q1.x + bb.z;
    o.w = (a[3] + c[3]) * inv + q1.y + bb.w;
    ((float4*)out)[(size_t)gw * 16 + sub] = o;
}

// ---------------------------------------------------------------------------
// Fused layer-1 + layer-2 GEMM (R10 version, measured best):
//   h = relu(BN([a16|x16] @ Wt1 + b1)) (smem only); [p16|q16] = h @ Wt2
// ---------------------------------------------------------------------------
#define ALDH 72
#define WLDH 136
#define CLD  136
#define BUFH (128 * ALDH + 64 * WLDH)        // 17920 halfs per buffer
#define HS_OFF   (2 * BUFH)
#define WT2_OFF  (HS_OFF + 128 * WLDH)
#define BN_BYTE  ((WT2_OFF + 128 * WLDH) * 2)
#define SM_BYTES (BN_BYTE + 1024)

__global__ void __launch_bounds__(256, 1) gemm12_kernel(
    const float* __restrict__ b1, const float* __restrict__ gmm,
    const float* __restrict__ bet, const float* __restrict__ mean,
    const float* __restrict__ var)
{
    extern __shared__ __align__(16) char smraw[];
    __half* smh = (__half*)smraw;
    float* Cs = (float*)smraw;                 // union with ping-pong buffers
    __half* Hs = smh + HS_OFF;
    __half* W2s = smh + WT2_OFF;
    float* Ssc = (float*)(smraw + BN_BYTE);
    float* Ssh = Ssc + 128;

    const int tid = threadIdx.x;
    const int wid = tid >> 5;
    const int wm = wid >> 1;
    const int wn = wid & 1;
    const int n0 = blockIdx.x * 128;
    const unsigned smu = (unsigned)__cvta_generic_to_shared(smraw);

    if (tid < 128) {
        float s = rsqrtf(var[tid] + 1e-5f) * gmm[tid];
        Ssc[tid] = s;
        Ssh[tid] = (b1[tid] - mean[tid]) * s + bet[tid];
    }

    wmma::fragment<wmma::accumulator, 16, 16, 16, float> acc[2][4];
#pragma unroll
    for (int i = 0; i < 2; i++)
#pragma unroll
        for (int j = 0; j < 4; j++) wmma::fill_fragment(acc[i][j], 0.f);

    const __half* A16 = g_a16;
    const __half* X16 = g_x16;
    const __half* WT = g_wt1h;

    auto stage = [&](int kc, int bufi) {
        unsigned base = smu + (unsigned)(bufi * BUFH * 2);
#pragma unroll
        for (int it = 0; it < 4; it++) {
            int t = tid + it * 256;          // 1024 chunks of 8 halfs
            int row = t >> 3, q = t & 7;
            int gn = n0 + row;
            unsigned dst = base + (unsigned)((row * ALDH + q * 8) * 2);
            if (kc < 2) {
                CPA16(dst, A16 + (size_t)gn * HID + kc * 64 + q * 8);
            } else {
                int sz = (gn < NN) ? 16 : 0;
                CPA16Z(dst, X16 + (size_t)gn * HID + (kc - 2) * 64 + q * 8, sz);
            }
        }
#pragma unroll
        for (int it = 0; it < 4; it++) {
            int t = tid + it * 256;          // 1024 chunks: 64 k-rows x 16
            int kr = t >> 4, fq = t & 15;
            unsigned dst = base + (unsigned)((128 * ALDH + kr * WLDH + fq * 8) * 2);
            CPA16(dst, WT + (size_t)(kc * 64 + kr) * HID + fq * 8);
        }
    };

    // prefetch Wt2 (128x128) into W2s as part of the first commit group
#pragma unroll
    for (int it = 0; it < 8; it++) {
        int t = tid + it * 256;              // 2048 chunks
        int kr = t >> 4, fq = t & 15;
        unsigned dst = smu + (unsigned)((WT2_OFF + kr * WLDH + fq * 8) * 2);
        CPA16(dst, g_wt2h + (size_t)kr * HID + fq * 8);
    }
    stage(0, 0);
    CPA_COMMIT();

    // ---- layer 1: K = 256 in 4 chunks of 64 ----
    for (int kc = 0; kc < 4; kc++) {
        int cur = kc & 1;
        if (kc < 3) stage(kc + 1, cur ^ 1);
        CPA_COMMIT();
        if (kc < 3) CPA_WAIT1(); else CPA_WAIT0();
        __syncthreads();

        __half* As = smh + cur * BUFH;
        __half* Ws = As + 128 * ALDH;
#pragma unroll
        for (int k16 = 0; k16 < 4; k16++) {
            wmma::fragment<wmma::matrix_a, 16, 16, 16, __half, wmma::row_major> a[2];
#pragma unroll
            for (int i = 0; i < 2; i++)
                wmma::load_matrix_sync(a[i], As + (wm * 32 + i * 16) * ALDH + k16 * 16, ALDH);
#pragma unroll
            for (int nf = 0; nf < 4; nf++) {
                wmma::fragment<wmma::matrix_b, 16, 16, 16, __half, wmma::row_major> b;
                wmma::load_matrix_sync(b, Ws + (k16 * 16) * WLDH + wn * 64 + nf * 16, WLDH);
#pragma unroll
                for (int i = 0; i < 2; i++)
                    wmma::mma_sync(acc[i][nf], a[i], b, acc[i][nf]);
            }
        }
        __syncthreads();
    }

    // ---- layer-1 epilogue: acc -> Cs -> BN+ReLU -> Hs (fp16, smem only) ----
#pragma unroll
    for (int i = 0; i < 2; i++)
#pragma unroll
        for (int nf = 0; nf < 4; nf++)
            wmma::store_matrix_sync(Cs + (wm * 32 + i * 16) * CLD + wn * 64 + nf * 16,
                                    acc[i][nf], CLD, wmma::mem_row_major);
    __syncthreads();
    {
        int row = tid >> 1, half = tid & 1;
        const float* src = Cs + row * CLD + half * 64;
        __half2* dst = (__half2*)(Hs + row * WLDH + half * 64);
#pragma unroll
        for (int j = 0; j < 16; j++) {
            float4 v = *(const float4*)(src + j * 4);
            int f = half * 64 + j * 4;
            float o0 = fmaxf(v.x * Ssc[f + 0] + Ssh[f + 0], 0.f);
            float o1 = fmaxf(v.y * Ssc[f + 1] + Ssh[f + 1], 0.f);
            float o2 = fmaxf(v.z * Ssc[f + 2] + Ssh[f + 2], 0.f);
            float o3 = fmaxf(v.w * Ssc[f + 3] + Ssh[f + 3], 0.f);
            dst[j * 2 + 0] = __floats2half2_rn(o0, o1);
            dst[j * 2 + 1] = __floats2half2_rn(o2, o3);
        }
    }
    __syncthreads();

    // ---- layer 2: [p|q] = Hs @ W2s (all operands in smem) ----
#pragma unroll
    for (int i = 0; i < 2; i++)
#pragma unroll
        for (int j = 0; j < 4; j++) wmma::fill_fragment(acc[i][j], 0.f);
#pragma unroll
    for (int k16 = 0; k16 < 8; k16++) {
        wmma::fragment<wmma::matrix_a, 16, 16, 16, __half, wmma::row_major> a[2];
#pragma unroll
        for (int i = 0; i < 2; i++)
            wmma::load_matrix_sync(a[i], Hs + (wm * 32 + i * 16) * WLDH + k16 * 16, WLDH);
#pragma unroll
        for (int nf = 0; nf < 4; nf++) {
            wmma::fragment<wmma::matrix_b, 16, 16, 16, __half, wmma::row_major> b;
            wmma::load_matrix_sync(b, W2s + (k16 * 16) * WLDH + wn * 64 + nf * 16, WLDH);
#pragma unroll
            for (int i = 0; i < 2; i++)
                wmma::mma_sync(acc[i][nf], a[i], b, acc[i][nf]);
        }
    }

    // ---- layer-2 epilogue: p cols [0,64) and q cols [64,128), both fp16 ----
#pragma unroll
    for (int i = 0; i < 2; i++)
#pragma unroll
        for (int nf = 0; nf < 4; nf++)
            wmma::store_matrix_sync(Cs + (wm * 32 + i * 16) * CLD + wn * 64 + nf * 16,
                                    acc[i][nf], CLD, wmma::mem_row_major);
    __syncthreads();
    {
        int row = tid >> 1, half = tid & 1;
        int gn = n0 + row;
        const float* src = Cs + row * CLD + half * 64;
        uint2* dst = half ? (uint2*)(g_q16 + (size_t)gn * OF)
                          : (uint2*)(g_p16 + (size_t)gn * OF);
#pragma unroll
        for (int j = 0; j < 16; j++) {
            float4 v = *(const float4*)(src + j * 4);
            __half2 h0 = __floats2half2_rn(v.x, v.y);
            __half2 h1 = __floats2half2_rn(v.z, v.w);
            uint2 u;
            u.x = *(unsigned*)&h0;
            u.y = *(unsigned*)&h1;
            dst[j] = u;
        }
    }
}

// ---------------------------------------------------------------------------
// Launch
// ---------------------------------------------------------------------------
extern "C" void kernel_launch(void* const* d_in, const int* in_sizes, int n_in,
                              void* d_out, int out_size) {
    const float* x    = (const float*)d_in[0];
    const void*  ei   = d_in[1];
    const float* W1l  = (const float*)d_in[2];
    const float* b1   = (const float*)d_in[3];
    const float* W1r  = (const float*)d_in[4];
    const float* gmm  = (const float*)d_in[5];
    const float* bet  = (const float*)d_in[6];
    const float* mean = (const float*)d_in[7];
    const float* var  = (const float*)d_in[8];
    const float* W2l  = (const float*)d_in[9];
    const float* b2   = (const float*)d_in[10];
    const float* W2r  = (const float*)d_in[11];
    float* out = (float*)d_out;

    cudaFuncSetAttribute(gemm12_kernel, cudaFuncAttributeMaxDynamicSharedMemorySize, SM_BYTES);

    void* degp = 0;
    void* bpackp = 0;
    cudaGetSymbolAddress(&degp, g_deg);
    cudaGetSymbolAddress(&bpackp, g_bpack);

    cudaMemsetAsync(degp, 0, sizeof(int) * NNP, 0);
    cudaMemsetAsync(bpackp, 0, sizeof(unsigned long long) * 128, 0);
    pre_kernel<<<PRE_GRID, 256>>>(x, ei, W1l, W1r, W2l, W2r);

    scan_kernel<<<98, 1024>>>();
    sort_kernel<<<(NE / 2 + 255) / 256, 256>>>(ei);
    agg1_kernel<<<NNP / 16, 256>>>();

    gemm12_kernel<<<NNP / 128, 256, SM_BYTES>>>(b1, gmm, bet, mean, var);
    agg2_final_kernel<<<(NN * 16 + 255) / 256, 256>>>(b2, out);
}